// round 16
// baseline (speedup 1.0000x reference)
#include <cuda_runtime.h>
#include <cuda_bf16.h>
#include <math_constants.h>

// MAGNN metapath attention aggregation, single pass over h_meta.
// h_meta [E,256] f32, attn_r [256] f32, dst [E] i32 (sorted asc), out [N,256] f32.
// H=8 heads, D=32 feats/head, leaky_relu 0.01, elu alpha=1.
//
// Persistent grid-stride warps (152x25 CTAs of 64 thr, 40 regs pinned ->
// all warps resident, no CTA churn). Each warp handles nodes gw, gw+W, ...
// and preloads the NEXT node's row_ptr pair at the top of the current body,
// hiding the inter-node startup chain. Per-node body = proven R12 code:
// prefetch.global.L1 at distance 3, no register double-buffer.
// No online max: logits ~ N(0,32); exp() safe in fp32, a/s identical math.

#define H 8
#define D 32
#define HD 256
#define NEG_SLOPE 0.01f
#define PF 3                    // prefetch distance in edges

#define MAX_NP1 (4 * 1024 * 1024)
__device__ int g_row_ptr[MAX_NP1];

// ---------------------------------------------------------------------------
// Kernel 1: row_ptr from sorted dst. row_ptr[v] = first edge with dst >= v.
// 4 edges per thread via one int4 load + one scalar (same-line) load.
// ---------------------------------------------------------------------------
__global__ void build_row_ptr_vec4(const int* __restrict__ dst, int E, int N) {
    int t  = blockIdx.x * blockDim.x + threadIdx.x;
    int e0 = t * 4;
    if (e0 >= E) return;

    int d0, d1, d2, d3;
    if (e0 + 3 < E) {
        int4 q = *reinterpret_cast<const int4*>(dst + e0);   // dst 16B-aligned
        d0 = q.x; d1 = q.y; d2 = q.z; d3 = q.w;
    } else {
        d0 = dst[e0];
        d1 = (e0 + 1 < E) ? dst[e0 + 1] : d0;
        d2 = (e0 + 2 < E) ? dst[e0 + 2] : d1;
        d3 = (e0 + 3 < E) ? dst[e0 + 3] : d2;
    }
    int dprev = (e0 == 0) ? -1 : dst[e0 - 1];   // neighbor's line -> cache hit

    for (int u = dprev + 1; u <= d0; ++u) g_row_ptr[u] = e0;
    if (e0 + 1 < E) for (int u = d0 + 1; u <= d1; ++u) g_row_ptr[u] = e0 + 1;
    if (e0 + 2 < E) for (int u = d1 + 1; u <= d2; ++u) g_row_ptr[u] = e0 + 2;
    if (e0 + 3 < E) for (int u = d2 + 1; u <= d3; ++u) g_row_ptr[u] = e0 + 3;

    int elast = min(e0 + 3, E - 1);
    if (elast == E - 1) {
        int dl = dst[E - 1];
        for (int u = dl + 1; u <= N; ++u) g_row_ptr[u] = E;
    }
}

// ---------------------------------------------------------------------------
// Kernel 2: persistent warps, grid-stride over nodes.
// Lane l: head=l>>2, d-slice=(l&3)*8 => row byte offset l*32.
// ---------------------------------------------------------------------------
__device__ __forceinline__ void prefetch_l1(const void* p) {
    asm volatile("prefetch.global.L1 [%0];" :: "l"(p));
}

__device__ __forceinline__ void edge_accum(
    const float4& a, const float4& b, const float ar[8],
    float& s, float acc[8])
{
    float hv[8] = {a.x, a.y, a.z, a.w, b.x, b.y, b.z, b.w};
    float p01 = fmaf(hv[1], ar[1], hv[0] * ar[0]);
    float p23 = fmaf(hv[3], ar[3], hv[2] * ar[2]);
    float p45 = fmaf(hv[5], ar[5], hv[4] * ar[4]);
    float p67 = fmaf(hv[7], ar[7], hv[6] * ar[6]);
    float part = (p01 + p23) + (p45 + p67);
    part += __shfl_xor_sync(0xFFFFFFFFu, part, 1);
    part += __shfl_xor_sync(0xFFFFFFFFu, part, 2);
    float lg = fmaxf(part, NEG_SLOPE * part);   // leaky_relu
    float p  = __expf(lg);                      // unnormalized weight
    s += p;
    #pragma unroll
    for (int i = 0; i < 8; ++i) acc[i] = fmaf(p, hv[i], acc[i]);
}

__global__ __launch_bounds__(64, 25)   // pin 40 regs: 25 CTAs x 2 warps resident
void magnn_persistent(const float* __restrict__ h_meta,
                      const float* __restrict__ attn_r,
                      float* __restrict__ out,
                      int N, int W) {
    const int lane = threadIdx.x & 31;
    const int gw   = blockIdx.x * (blockDim.x >> 5) + (threadIdx.x >> 5);

    const float4* ar4 = reinterpret_cast<const float4*>(attn_r + lane * 8);
    float4 arA = __ldg(ar4);
    float4 arB = __ldg(ar4 + 1);
    const float ar[8] = {arA.x, arA.y, arA.z, arA.w, arB.x, arB.y, arB.z, arB.w};

    const char* base = reinterpret_cast<const char*>(h_meta) + (size_t)lane * 32;
    auto rowA = [&](int e) {
        return __ldg(reinterpret_cast<const float4*>(base + (size_t)e * (HD * 4)));
    };
    auto rowB = [&](int e) {
        return __ldg(reinterpret_cast<const float4*>(base + (size_t)e * (HD * 4) + 16));
    };

    int v = gw;
    if (v >= N) return;
    int beg = g_row_ptr[v];
    int end = g_row_ptr[v + 1];

    while (true) {
        // preload NEXT node's boundaries; completes during this node's body
        const int vn = v + W;
        int nbeg = 0, nend = 0;
        if (vn < N) {
            nbeg = g_row_ptr[vn];
            nend = g_row_ptr[vn + 1];
        }

        float4* orow = reinterpret_cast<float4*>(out + (size_t)v * HD + lane * 8);

        if (beg >= end) {   // degree 0: elu(0)=0; out is poisoned -> write zeros
            float4 z = make_float4(0.f, 0.f, 0.f, 0.f);
            orow[0] = z;
            orow[1] = z;
        } else {
            const int last = end - 1;
            prefetch_l1(base + (size_t)beg * (HD * 4));
            prefetch_l1(base + (size_t)min(beg + 1, last) * (HD * 4));
            prefetch_l1(base + (size_t)min(beg + 2, last) * (HD * 4));

            float s = 0.0f;
            float acc[8] = {0.f, 0.f, 0.f, 0.f, 0.f, 0.f, 0.f, 0.f};

            #pragma unroll 2
            for (int e = beg; e < end; ++e) {
                prefetch_l1(base + (size_t)min(e + PF, last) * (HD * 4));
                float4 a = rowA(e);
                float4 b = rowB(e);
                edge_accum(a, b, ar, s, acc);
            }

            float inv = 1.0f / s;
            float r[8];
            #pragma unroll
            for (int i = 0; i < 8; ++i) {
                float x = acc[i] * inv;
                r[i] = (x > 0.f) ? x : expm1f(x);   // elu
            }
            orow[0] = make_float4(r[0], r[1], r[2], r[3]);
            orow[1] = make_float4(r[4], r[5], r[6], r[7]);
        }

        if (vn >= N) break;
        v = vn; beg = nbeg; end = nend;
    }
}

// ---------------------------------------------------------------------------
extern "C" void kernel_launch(void* const* d_in, const int* in_sizes, int n_in,
                              void* d_out, int out_size) {
    const float* h_meta = (const float*)d_in[0];
    const float* attn_r = (const float*)d_in[1];
    const int*   dst    = (const int*)d_in[2];

    const int E = in_sizes[2];
    const int N = out_size / HD;

    {
        int threads = 256;
        int edges_per_blk = threads * 4;
        int blocks = (E + edges_per_blk - 1) / edges_per_blk;
        build_row_ptr_vec4<<<blocks, threads>>>(dst, E, N);
    }
    {
        // persistent single wave: 152 SMs x 25 CTAs x 2 warps = 7600 warps,
        // all resident at 40 regs (pinned via launch bounds).
        const int threads = 64;
        const int blocks  = 152 * 25;
        const int W = blocks * (threads / 32);
        magnn_persistent<<<blocks, threads>>>(h_meta, attn_r, (float*)d_out, N, W);
    }
}

// round 17
// speedup vs baseline: 1.6092x; 1.6092x over previous
#include <cuda_runtime.h>
#include <cuda_bf16.h>
#include <math_constants.h>

// MAGNN metapath attention aggregation, single fused kernel, single pass.
// h_meta [E,256] f32, attn_r [256] f32, dst [E] i32 (sorted asc), out [N,256] f32.
// H=8 heads, D=32 feats/head, leaky_relu 0.01, elu alpha=1.
//
// Warp-per-node (2-warp CTAs), R15 hot loop (prefetch.global.L1 @ distance 3,
// no register double-buffer, natural ~40 regs). Edge range [beg,end) for the
// warp's node is computed IN-WARP from sorted dst:
//   beg = warp-cooperative 32-ary lower_bound (4 rounds + final ballot)
//   end = ballot scan over dst[beg+lane]
// -> no CSR build kernel, no scratch, one launch.
// No online max: logits ~ N(0,32); exp() safe in fp32, a/s identical math.

#define H 8
#define D 32
#define HD 256
#define NEG_SLOPE 0.01f
#define PF 3                    // prefetch distance in edges

// ---------------------------------------------------------------------------
// Warp-cooperative lower_bound: first i in [0,E] with dst[i] >= v.
// Invariants: dst[lo] < v (virtual dst[-1]=-inf), dst[hi] >= v (virtual dst[E]=+inf).
// Each round 32 probes shrink span by ~33x: 1M -> <=32 in 4 rounds.
// ---------------------------------------------------------------------------
__device__ __forceinline__ int warp_lower_bound(const int* __restrict__ dst,
                                                int E, int v, int lane) {
    int lo = -1;
    int hi = E;
    while (hi - lo > 32) {
        int span = hi - lo;
        int step = span / 33 + 1;
        int p = lo + (lane + 1) * step;
        bool valid = p < hi;
        bool pred  = valid && (__ldg(dst + (valid ? p : 0)) >= v);
        unsigned mt = __ballot_sync(0xFFFFFFFFu, pred);
        unsigned mv = __ballot_sync(0xFFFFFFFFu, valid);
        if (mt) {
            int t = __ffs(mt) - 1;          // first true probe
            hi = lo + (t + 1) * step;
            lo = lo + t * step;             // t==0 leaves lo unchanged
        } else {
            lo = lo + __popc(mv) * step;    // past the last (false) valid probe
        }
    }
    // span <= 32: probes lo+1+lane cover (lo, hi]; p >= hi counts as true
    int p = lo + 1 + lane;
    bool pred = (p >= hi) || (__ldg(dst + p) >= v);   // p < hi <= E -> p <= E-1
    unsigned m = __ballot_sync(0xFFFFFFFFu, pred);    // nonzero (lane31 p>=hi)
    return lo + 1 + (__ffs(m) - 1);
}

// end of segment for value v starting at beg (dst sorted, dst[beg..] >= v)
__device__ __forceinline__ int warp_segment_end(const int* __restrict__ dst,
                                                int E, int v, int beg, int lane) {
    int end = beg;
    while (true) {
        int p = end + lane;
        bool gt = (p >= E) || (__ldg(dst + p) > v);
        unsigned m = __ballot_sync(0xFFFFFFFFu, gt);
        if (m) return end + (__ffs(m) - 1);
        end += 32;                          // degree >= 32 (astronomically rare)
    }
}

// ---------------------------------------------------------------------------
// Fused kernel: warp per node. Lane l: head=l>>2, d-slice=(l&3)*8 => byte l*32.
// ---------------------------------------------------------------------------
__device__ __forceinline__ void prefetch_l1(const void* p) {
    asm volatile("prefetch.global.L1 [%0];" :: "l"(p));
}

__device__ __forceinline__ void edge_accum(
    const float4& a, const float4& b, const float ar[8],
    float& s, float acc[8])
{
    float hv[8] = {a.x, a.y, a.z, a.w, b.x, b.y, b.z, b.w};
    float p01 = fmaf(hv[1], ar[1], hv[0] * ar[0]);
    float p23 = fmaf(hv[3], ar[3], hv[2] * ar[2]);
    float p45 = fmaf(hv[5], ar[5], hv[4] * ar[4]);
    float p67 = fmaf(hv[7], ar[7], hv[6] * ar[6]);
    float part = (p01 + p23) + (p45 + p67);
    part += __shfl_xor_sync(0xFFFFFFFFu, part, 1);
    part += __shfl_xor_sync(0xFFFFFFFFu, part, 2);
    float lg = fmaxf(part, NEG_SLOPE * part);   // leaky_relu
    float p  = __expf(lg);                      // unnormalized weight
    s += p;
    #pragma unroll
    for (int i = 0; i < 8; ++i) acc[i] = fmaf(p, hv[i], acc[i]);
}

__global__ __launch_bounds__(64)
void magnn_fused(const float* __restrict__ h_meta,
                 const float* __restrict__ attn_r,
                 const int*   __restrict__ dst,
                 float* __restrict__ out,
                 int N, int E) {
    const int warp_in_blk = threadIdx.x >> 5;
    const int lane        = threadIdx.x & 31;
    const int node        = blockIdx.x * (blockDim.x >> 5) + warp_in_blk;
    if (node >= N) return;

    // in-warp CSR: beg/end from sorted dst (replaces the build_row_ptr kernel)
    const int beg = warp_lower_bound(dst, E, node, lane);
    const int end = warp_segment_end(dst, E, node, beg, lane);

    const float4* ar4 = reinterpret_cast<const float4*>(attn_r + lane * 8);
    float4 arA = __ldg(ar4);
    float4 arB = __ldg(ar4 + 1);
    const float ar[8] = {arA.x, arA.y, arA.z, arA.w, arB.x, arB.y, arB.z, arB.w};

    float4* orow = reinterpret_cast<float4*>(out + (size_t)node * HD + lane * 8);

    if (beg >= end) {   // degree 0: sums are 0, elu(0)=0; out is poisoned
        float4 z = make_float4(0.f, 0.f, 0.f, 0.f);
        orow[0] = z;
        orow[1] = z;
        return;
    }

    const char* base = reinterpret_cast<const char*>(h_meta) + (size_t)lane * 32;
    auto rowA = [&](int e) {
        return __ldg(reinterpret_cast<const float4*>(base + (size_t)e * (HD * 4)));
    };
    auto rowB = [&](int e) {
        return __ldg(reinterpret_cast<const float4*>(base + (size_t)e * (HD * 4) + 16));
    };

    // warm the first PF edges' lines (clamped; redundant prefetch harmless)
    const int last = end - 1;
    prefetch_l1(base + (size_t)beg * (HD * 4));
    prefetch_l1(base + (size_t)min(beg + 1, last) * (HD * 4));
    prefetch_l1(base + (size_t)min(beg + 2, last) * (HD * 4));

    float s = 0.0f;
    float acc[8] = {0.f, 0.f, 0.f, 0.f, 0.f, 0.f, 0.f, 0.f};

    #pragma unroll 2
    for (int e = beg; e < end; ++e) {
        // prefetch edge e+PF (clamped -> tail prefetches are L1 hits)
        prefetch_l1(base + (size_t)min(e + PF, last) * (HD * 4));

        float4 a = rowA(e);
        float4 b = rowB(e);
        edge_accum(a, b, ar, s, acc);
    }

    float inv = 1.0f / s;
    float r[8];
    #pragma unroll
    for (int i = 0; i < 8; ++i) {
        float x = acc[i] * inv;
        r[i] = (x > 0.f) ? x : expm1f(x);   // elu
    }
    orow[0] = make_float4(r[0], r[1], r[2], r[3]);
    orow[1] = make_float4(r[4], r[5], r[6], r[7]);
}

// ---------------------------------------------------------------------------
extern "C" void kernel_launch(void* const* d_in, const int* in_sizes, int n_in,
                              void* d_out, int out_size) {
    const float* h_meta = (const float*)d_in[0];
    const float* attn_r = (const float*)d_in[1];
    const int*   dst    = (const int*)d_in[2];

    const int E = in_sizes[2];
    const int N = out_size / HD;

    // single fused launch: 2 warps per CTA, warp per node
    const int threads = 64;
    const int warps_per_blk = threads / 32;
    const int blocks = (N + warps_per_blk - 1) / warps_per_blk;
    magnn_fused<<<blocks, threads>>>(h_meta, attn_r, dst, (float*)d_out, N, E);
}